// round 5
// baseline (speedup 1.0000x reference)
#include <cuda_runtime.h>
#include <cuda_bf16.h>
#include <cstdint>

#define T_STEPS 4096
#define ISZ 512
#define HSZ 2048
#define GSZ (4*HSZ)          // 8192 gate rows
#define NBLK 148             // persistent CTAs (1 per SM, forced by smem)
#define NTHR 512
#define RMAX 56              // padded gate rows per CTA (4*14)

// ---------------- static device scratch (no allocations allowed) ------------
__device__ float g_X[(size_t)T_STEPS * GSZ];   // precomputed input gates
__device__ float g_h[2][HSZ];                  // double-buffered hidden state
__device__ unsigned g_stamp[NBLK * 8];         // per-CTA stamps, 32B apart

// ---------------- flag ops --------------------------------------------------
__device__ __forceinline__ unsigned ld_relaxed_gpu(const unsigned* p) {
    unsigned v;
    asm volatile("ld.relaxed.gpu.global.u32 %0, [%1];"
                 : "=r"(v) : "l"(p) : "memory");
    return v;
}
__device__ __forceinline__ void st_release_gpu(unsigned* p, unsigned v) {
    asm volatile("st.release.gpu.global.u32 [%0], %1;"
                 :: "l"(p), "r"(v) : "memory");
}

// Single-hop all-to-all grid barrier.
// Producer: __syncthreads (orders h stores CTA-wide), thread0 st.release stamp.
// Consumers: threads 0..147 relaxed-poll one stamp each; on success each poller
// executes fence.acq_rel.gpu (relaxed-read + fence = acquire pattern, morally
// strong), then bar.sync propagates the ordering CTA-wide. Stamps are
// monotonic within a launch; reset by final_linear for graph-replay determinism.
__device__ __forceinline__ void grid_barrier(int b, unsigned stamp) {
    __syncthreads();
    if (threadIdx.x == 0)
        st_release_gpu(&g_stamp[b * 8], stamp);
    if (threadIdx.x < NBLK) {
        while (ld_relaxed_gpu(&g_stamp[threadIdx.x * 8]) < stamp) { }
        asm volatile("fence.acq_rel.gpu;" ::: "memory");
    }
    __syncthreads();
}

// ====================== Kernel 1: X = input @ W_ih^T + (b_ih+b_hh) ==========
#define BM 128
#define BN 128
#define BK 16

__global__ void __launch_bounds__(256) gemm_xgates(
    const float* __restrict__ A, const float* __restrict__ B,
    const float* __restrict__ b_ih, const float* __restrict__ b_hh)
{
    __shared__ float As[BK][BM];
    __shared__ float Bs[BK][BN];
    const int tid = threadIdx.x;
    const int tx = tid & 15, ty = tid >> 4;
    const int m0 = blockIdx.y * BM, n0 = blockIdx.x * BN;
    float acc[8][8] = {};

    for (int k0 = 0; k0 < ISZ; k0 += BK) {
        #pragma unroll
        for (int rep = 0; rep < 2; rep++) {
            int row = (tid >> 2) + rep * 64;
            int kg  = (tid & 3) * 4;
            float4 va = *(const float4*)&A[(size_t)(m0 + row) * ISZ + k0 + kg];
            As[kg+0][row] = va.x; As[kg+1][row] = va.y;
            As[kg+2][row] = va.z; As[kg+3][row] = va.w;
            float4 vb = *(const float4*)&B[(size_t)(n0 + row) * ISZ + k0 + kg];
            Bs[kg+0][row] = vb.x; Bs[kg+1][row] = vb.y;
            Bs[kg+2][row] = vb.z; Bs[kg+3][row] = vb.w;
        }
        __syncthreads();
        #pragma unroll
        for (int kk = 0; kk < BK; kk++) {
            float a[8], bb[8];
            float4 a0 = *(const float4*)&As[kk][ty * 8];
            float4 a1 = *(const float4*)&As[kk][ty * 8 + 4];
            float4 b0 = *(const float4*)&Bs[kk][tx * 8];
            float4 b1 = *(const float4*)&Bs[kk][tx * 8 + 4];
            a[0]=a0.x; a[1]=a0.y; a[2]=a0.z; a[3]=a0.w;
            a[4]=a1.x; a[5]=a1.y; a[6]=a1.z; a[7]=a1.w;
            bb[0]=b0.x; bb[1]=b0.y; bb[2]=b0.z; bb[3]=b0.w;
            bb[4]=b1.x; bb[5]=b1.y; bb[6]=b1.z; bb[7]=b1.w;
            #pragma unroll
            for (int i = 0; i < 8; i++)
                #pragma unroll
                for (int j = 0; j < 8; j++)
                    acc[i][j] += a[i] * bb[j];
        }
        __syncthreads();
    }
    #pragma unroll
    for (int i = 0; i < 8; i++) {
        int m = m0 + ty * 8 + i;
        #pragma unroll
        for (int j = 0; j < 8; j++) {
            int n = n0 + tx * 8 + j;
            g_X[(size_t)m * GSZ + n] = acc[i][j] + b_ih[n] + b_hh[n];
        }
    }
}

// ====================== Kernel 2: persistent recurrence =====================
__device__ __forceinline__ float sigf(float x) { return 1.f / (1.f + __expf(-x)); }

template<int U>
__device__ __forceinline__ void lstm_body(const int b, const int u0,
                                          const float* __restrict__ W_hh)
{
    constexpr int R = 4 * U;          // live gate rows (52 or 56)
    extern __shared__ unsigned smem[];
    unsigned* sw = smem;                              // [RMAX][1024] bf16x2
    float* sacc  = (float*)(smem + RMAX * 1024);      // [4][RMAX] partials

    const int tid = threadIdx.x;

    // ---- stage W_hh slice as packed bf16 pairs; pad rows >= R with zeros ----
    // uint j of row r holds global columns 2j, 2j+1.
    for (int idx = tid; idx < RMAX * 1024; idx += NTHR) {
        const int r  = idx >> 10;
        const int k2 = idx & 1023;
        unsigned packed = 0u;
        if (r < R) {
            const int grow = (r / U) * HSZ + u0 + (r % U);
            float2 w2 = *(const float2*)&W_hh[(size_t)grow * HSZ + 2 * k2];
            unsigned lo = (unsigned)__bfloat16_as_ushort(__float2bfloat16(w2.x));
            unsigned hi = (unsigned)__bfloat16_as_ushort(__float2bfloat16(w2.y));
            packed = (hi << 16) | lo;
        }
        sw[idx] = packed;
    }
    float c_state = 0.f;
    if (tid < U) g_h[0][u0 + tid] = 0.f;
    grid_barrier(b, 1u);

    const int w = tid >> 5, l = tid & 31;
    const int kq = w >> 2;            // K quarter (0..3), 512 columns each
    const int wr = w & 3;             // row slot (0..3)
    const uint4* wbase = (const uint4*)sw;

    for (int t = 0; t < T_STEPS; t++) {
        // -- prefetch this step's x-gate terms (DRAM latency hides under MAC)
        float xgi = 0.f, xgf = 0.f, xgg = 0.f, xgo = 0.f;
        if (tid < U) {
            const float* xg = &g_X[(size_t)t * GSZ + u0 + tid];
            xgi = __ldcs(xg);
            xgf = __ldcs(xg + HSZ);
            xgg = __ldcs(xg + 2 * HSZ);
            xgo = __ldcs(xg + 3 * HSZ);
        }

        // -- load this warp's 512-wide h quarter: lane l owns
        //    in-quarter cols [8l..8l+7] and [256+8l..256+8l+7]
        float h[16];
        {
            const float4* hb = (const float4*)&g_h[t & 1][kq * 512];
            float4 a0 = __ldcg(hb + l * 2);
            float4 a1 = __ldcg(hb + l * 2 + 1);
            float4 a2 = __ldcg(hb + 64 + l * 2);
            float4 a3 = __ldcg(hb + 64 + l * 2 + 1);
            h[0]=a0.x;  h[1]=a0.y;  h[2]=a0.z;  h[3]=a0.w;
            h[4]=a1.x;  h[5]=a1.y;  h[6]=a1.z;  h[7]=a1.w;
            h[8]=a2.x;  h[9]=a2.y;  h[10]=a2.z; h[11]=a2.w;
            h[12]=a3.x; h[13]=a3.y; h[14]=a3.z; h[15]=a3.w;
        }

        // -- MAC phase: 14 independent rows per warp, fully unrolled ---------
        #pragma unroll
        for (int rr = 0; rr < 14; rr++) {
            const int r = wr + rr * 4;
            // row r, quarter kq: uint4 base index r*256 + kq*64
            const uint4* wp = wbase + r * 256 + kq * 64 + l;
            float acc0 = 0.f, acc1 = 0.f;
            uint4 q0 = wp[0];      // in-quarter cols 8l..8l+7
            acc0 += __uint_as_float(q0.x << 16)         * h[0];
            acc1 += __uint_as_float(q0.x & 0xFFFF0000u) * h[1];
            acc0 += __uint_as_float(q0.y << 16)         * h[2];
            acc1 += __uint_as_float(q0.y & 0xFFFF0000u) * h[3];
            acc0 += __uint_as_float(q0.z << 16)         * h[4];
            acc1 += __uint_as_float(q0.z & 0xFFFF0000u) * h[5];
            acc0 += __uint_as_float(q0.w << 16)         * h[6];
            acc1 += __uint_as_float(q0.w & 0xFFFF0000u) * h[7];
            uint4 q1 = wp[32];     // in-quarter cols 256+8l..
            acc0 += __uint_as_float(q1.x << 16)         * h[8];
            acc1 += __uint_as_float(q1.x & 0xFFFF0000u) * h[9];
            acc0 += __uint_as_float(q1.y << 16)         * h[10];
            acc1 += __uint_as_float(q1.y & 0xFFFF0000u) * h[11];
            acc0 += __uint_as_float(q1.z << 16)         * h[12];
            acc1 += __uint_as_float(q1.z & 0xFFFF0000u) * h[13];
            acc0 += __uint_as_float(q1.w << 16)         * h[14];
            acc1 += __uint_as_float(q1.w & 0xFFFF0000u) * h[15];
            float acc = acc0 + acc1;
            #pragma unroll
            for (int s = 16; s > 0; s >>= 1)
                acc += __shfl_xor_sync(0xffffffffu, acc, s);
            if (l == 0) sacc[kq * RMAX + r] = acc;     // per-quarter, no atomics
        }
        __syncthreads();

        // -- epilogue: gates -> (c, h) for this CTA's units -------------------
        if (tid < U) {
            float gi = xgi, gf = xgf, gg = xgg, go = xgo;
            #pragma unroll
            for (int q = 0; q < 4; q++) {
                gi += sacc[q * RMAX + 0*U + tid];
                gf += sacc[q * RMAX + 1*U + tid];
                gg += sacc[q * RMAX + 2*U + tid];
                go += sacc[q * RMAX + 3*U + tid];
            }
            float ig = sigf(gi);
            float fg = sigf(gf);
            float gt = tanhf(gg);
            float og = sigf(go);
            c_state = fg * c_state + ig * gt;
            g_h[(t + 1) & 1][u0 + tid] = og * tanhf(c_state);
        }
        grid_barrier(b, (unsigned)(t + 2));
    }
}

__global__ void __launch_bounds__(NTHR) lstm_recurrent(const float* __restrict__ W_hh)
{
    const int b = blockIdx.x;
    if (b < 124) lstm_body<14>(b, b * 14, W_hh);
    else         lstm_body<13>(b, 124 * 14 + (b - 124) * 13, W_hh);
}

// ====================== Kernel 3: out = h_T @ W_lin^T + b_lin ===============
__global__ void __launch_bounds__(256) final_linear(
    const float* __restrict__ W_lin, const float* __restrict__ b_lin, float* out)
{
    __shared__ float red[256];
    float s = 0.f;
    // T_STEPS even -> final h lives in buffer 0
    for (int k = threadIdx.x; k < HSZ; k += 256)
        s += g_h[0][k] * W_lin[k];
    red[threadIdx.x] = s;
    __syncthreads();
    for (int o = 128; o > 0; o >>= 1) {
        if (threadIdx.x < o) red[threadIdx.x] += red[threadIdx.x + o];
        __syncthreads();
    }
    if (threadIdx.x == 0) out[0] = red[0] + b_lin[0];

    // reset barrier state so graph replays are deterministic
    for (int i = threadIdx.x; i < NBLK * 8; i += 256) g_stamp[i] = 0u;
}

// ============================================================================
extern "C" void kernel_launch(void* const* d_in, const int* in_sizes, int n_in,
                              void* d_out, int out_size)
{
    const float* input = (const float*)d_in[0];
    const float* W_ih  = (const float*)d_in[1];
    const float* W_hh  = (const float*)d_in[2];
    const float* b_ih  = (const float*)d_in[3];
    const float* b_hh  = (const float*)d_in[4];
    const float* W_lin = (const float*)d_in[5];
    const float* b_lin = (const float*)d_in[6];

    dim3 g1(GSZ / BN, T_STEPS / BM);
    gemm_xgates<<<g1, 256>>>(input, W_ih, b_ih, b_hh);

    const int smem_bytes = RMAX * 1024 * 4 + 4 * RMAX * 4;   // 230,272 B
    cudaFuncSetAttribute(lstm_recurrent,
                         cudaFuncAttributeMaxDynamicSharedMemorySize, smem_bytes);
    lstm_recurrent<<<NBLK, NTHR, smem_bytes>>>(W_hh);

    final_linear<<<1, 256>>>(W_lin, b_lin, (float*)d_out);
}

// round 6
// speedup vs baseline: 1.1300x; 1.1300x over previous
#include <cuda_runtime.h>
#include <cuda_bf16.h>
#include <cstdint>

#define T_STEPS 4096
#define ISZ 512
#define HSZ 2048
#define GSZ (4*HSZ)          // 8192 gate rows
#define NBLK 148             // persistent CTAs (1 per SM, forced by smem)
#define NTHR 512
#define RMAX 56              // padded gate rows per CTA (4*14)

// ---------------- static device scratch (no allocations allowed) ------------
__device__ float g_X[(size_t)T_STEPS * GSZ];   // precomputed input gates
__device__ float g_h[2][HSZ];                  // double-buffered hidden state
__device__ unsigned g_cnt[8 * 32];             // 8 arrival counters, 128B apart
__device__ unsigned g_rel[NBLK * 32];          // per-CTA release lines, 128B apart

// ---------------- flag ops --------------------------------------------------
__device__ __forceinline__ void red_release_add(unsigned* p, unsigned v) {
    asm volatile("red.release.gpu.global.add.u32 [%0], %1;"
                 :: "l"(p), "r"(v) : "memory");
}
__device__ __forceinline__ unsigned ld_relaxed_gpu(const unsigned* p) {
    unsigned v;
    asm volatile("ld.relaxed.gpu.global.u32 %0, [%1];"
                 : "=r"(v) : "l"(p) : "memory");
    return v;
}
__device__ __forceinline__ void st_release_gpu(unsigned* p, unsigned v) {
    asm volatile("st.release.gpu.global.u32 [%0], %1;"
                 :: "l"(p), "r"(v) : "memory");
}
__device__ __forceinline__ void fence_acq() {
    asm volatile("fence.acq_rel.gpu;" ::: "memory");
}

// Grid barrier, contention-minimized:
//  arrive : thread0 red.release.add onto 1 of 8 spread counters
//  check  : CTA0 threads 0..7 relaxed-poll counters (+acquire fence)
//  release: CTA0 threads 0..147 st.release stamp to 148 private lines
//  wait   : each CTA's thread0 relaxed-polls ITS OWN line (1 reader/line)
// Release-acquire chain is transitive (morally strong at every hop), so h
// stores made before arrival are visible after the wait. Counters and release
// words are monotonic within a launch; final_linear resets them so graph
// replays are deterministic.
__device__ __forceinline__ void grid_barrier(int b, unsigned stamp) {
    __syncthreads();
    if (threadIdx.x == 0)
        red_release_add(&g_cnt[(b & 7) * 32], 1u);
    if (b == 0) {
        if (threadIdx.x < 8) {
            const unsigned gsz  = (threadIdx.x < 4) ? 19u : 18u;  // 148=4*19+4*18
            const unsigned need = stamp * gsz;
            while (ld_relaxed_gpu(&g_cnt[threadIdx.x * 32]) < need) { }
            fence_acq();
        }
        __syncthreads();
        if (threadIdx.x < NBLK)
            st_release_gpu(&g_rel[threadIdx.x * 32], stamp);
    }
    if (threadIdx.x == 0) {
        while (ld_relaxed_gpu(&g_rel[b * 32]) < stamp) { }
        fence_acq();
    }
    __syncthreads();
}

// ====================== Kernel 1: X = input @ W_ih^T + (b_ih+b_hh) ==========
#define BM 128
#define BN 128
#define BK 16

__global__ void __launch_bounds__(256) gemm_xgates(
    const float* __restrict__ A, const float* __restrict__ B,
    const float* __restrict__ b_ih, const float* __restrict__ b_hh)
{
    __shared__ float As[BK][BM];
    __shared__ float Bs[BK][BN];
    const int tid = threadIdx.x;
    const int tx = tid & 15, ty = tid >> 4;
    const int m0 = blockIdx.y * BM, n0 = blockIdx.x * BN;
    float acc[8][8] = {};

    for (int k0 = 0; k0 < ISZ; k0 += BK) {
        #pragma unroll
        for (int rep = 0; rep < 2; rep++) {
            int row = (tid >> 2) + rep * 64;
            int kg  = (tid & 3) * 4;
            float4 va = *(const float4*)&A[(size_t)(m0 + row) * ISZ + k0 + kg];
            As[kg+0][row] = va.x; As[kg+1][row] = va.y;
            As[kg+2][row] = va.z; As[kg+3][row] = va.w;
            float4 vb = *(const float4*)&B[(size_t)(n0 + row) * ISZ + k0 + kg];
            Bs[kg+0][row] = vb.x; Bs[kg+1][row] = vb.y;
            Bs[kg+2][row] = vb.z; Bs[kg+3][row] = vb.w;
        }
        __syncthreads();
        #pragma unroll
        for (int kk = 0; kk < BK; kk++) {
            float a[8], bb[8];
            float4 a0 = *(const float4*)&As[kk][ty * 8];
            float4 a1 = *(const float4*)&As[kk][ty * 8 + 4];
            float4 b0 = *(const float4*)&Bs[kk][tx * 8];
            float4 b1 = *(const float4*)&Bs[kk][tx * 8 + 4];
            a[0]=a0.x; a[1]=a0.y; a[2]=a0.z; a[3]=a0.w;
            a[4]=a1.x; a[5]=a1.y; a[6]=a1.z; a[7]=a1.w;
            bb[0]=b0.x; bb[1]=b0.y; bb[2]=b0.z; bb[3]=b0.w;
            bb[4]=b1.x; bb[5]=b1.y; bb[6]=b1.z; bb[7]=b1.w;
            #pragma unroll
            for (int i = 0; i < 8; i++)
                #pragma unroll
                for (int j = 0; j < 8; j++)
                    acc[i][j] += a[i] * bb[j];
        }
        __syncthreads();
    }
    #pragma unroll
    for (int i = 0; i < 8; i++) {
        int m = m0 + ty * 8 + i;
        #pragma unroll
        for (int j = 0; j < 8; j++) {
            int n = n0 + tx * 8 + j;
            g_X[(size_t)m * GSZ + n] = acc[i][j] + b_ih[n] + b_hh[n];
        }
    }
}

// ====================== Kernel 2: persistent recurrence =====================
__device__ __forceinline__ float sigf(float x) { return 1.f / (1.f + __expf(-x)); }

template<int U>
__device__ __forceinline__ void lstm_body(const int b, const int u0,
                                          const float* __restrict__ W_hh)
{
    constexpr int R = 4 * U;          // live gate rows (52 or 56)
    extern __shared__ unsigned smem[];
    unsigned* sw = smem;                              // [RMAX][1024] bf16x2
    float* sacc  = (float*)(smem + RMAX * 1024);      // [4][RMAX] partials

    const int tid = threadIdx.x;

    // ---- stage W_hh slice as packed bf16 pairs; pad rows >= R with zeros ----
    for (int idx = tid; idx < RMAX * 1024; idx += NTHR) {
        const int r  = idx >> 10;
        const int k2 = idx & 1023;
        unsigned packed = 0u;
        if (r < R) {
            const int grow = (r / U) * HSZ + u0 + (r % U);
            float2 w2 = *(const float2*)&W_hh[(size_t)grow * HSZ + 2 * k2];
            unsigned lo = (unsigned)__bfloat16_as_ushort(__float2bfloat16(w2.x));
            unsigned hi = (unsigned)__bfloat16_as_ushort(__float2bfloat16(w2.y));
            packed = (hi << 16) | lo;
        }
        sw[idx] = packed;
    }
    float c_state = 0.f;
    if (tid < U) g_h[0][u0 + tid] = 0.f;
    grid_barrier(b, 1u);

    const int w = tid >> 5, l = tid & 31;
    const int kq = w >> 2;            // K quarter (0..3), 512 columns each
    const int wr = w & 3;             // row slot (0..3)
    const uint4* wbase = (const uint4*)sw;

    for (int t = 0; t < T_STEPS; t++) {
        // -- prefetch this step's x-gate terms (DRAM latency hides under MAC)
        float xgi = 0.f, xgf = 0.f, xgg = 0.f, xgo = 0.f;
        if (tid < U) {
            const float* xg = &g_X[(size_t)t * GSZ + u0 + tid];
            xgi = __ldcs(xg);
            xgf = __ldcs(xg + HSZ);
            xgg = __ldcs(xg + 2 * HSZ);
            xgo = __ldcs(xg + 3 * HSZ);
        }

        // -- load this warp's 512-wide h quarter: lane l owns
        //    in-quarter cols [8l..8l+7] and [256+8l..256+8l+7]
        float h[16];
        {
            const float4* hb = (const float4*)&g_h[t & 1][kq * 512];
            float4 a0 = __ldcg(hb + l * 2);
            float4 a1 = __ldcg(hb + l * 2 + 1);
            float4 a2 = __ldcg(hb + 64 + l * 2);
            float4 a3 = __ldcg(hb + 64 + l * 2 + 1);
            h[0]=a0.x;  h[1]=a0.y;  h[2]=a0.z;  h[3]=a0.w;
            h[4]=a1.x;  h[5]=a1.y;  h[6]=a1.z;  h[7]=a1.w;
            h[8]=a2.x;  h[9]=a2.y;  h[10]=a2.z; h[11]=a2.w;
            h[12]=a3.x; h[13]=a3.y; h[14]=a3.z; h[15]=a3.w;
        }

        // -- MAC phase: 14 independent rows per warp, fully unrolled ---------
        #pragma unroll
        for (int rr = 0; rr < 14; rr++) {
            const int r = wr + rr * 4;
            const uint4* wp = wbase + r * 256 + kq * 64 + l;
            float acc0 = 0.f, acc1 = 0.f;
            uint4 q0 = wp[0];
            acc0 += __uint_as_float(q0.x << 16)         * h[0];
            acc1 += __uint_as_float(q0.x & 0xFFFF0000u) * h[1];
            acc0 += __uint_as_float(q0.y << 16)         * h[2];
            acc1 += __uint_as_float(q0.y & 0xFFFF0000u) * h[3];
            acc0 += __uint_as_float(q0.z << 16)         * h[4];
            acc1 += __uint_as_float(q0.z & 0xFFFF0000u) * h[5];
            acc0 += __uint_as_float(q0.w << 16)         * h[6];
            acc1 += __uint_as_float(q0.w & 0xFFFF0000u) * h[7];
            uint4 q1 = wp[32];
            acc0 += __uint_as_float(q1.x << 16)         * h[8];
            acc1 += __uint_as_float(q1.x & 0xFFFF0000u) * h[9];
            acc0 += __uint_as_float(q1.y << 16)         * h[10];
            acc1 += __uint_as_float(q1.y & 0xFFFF0000u) * h[11];
            acc0 += __uint_as_float(q1.z << 16)         * h[12];
            acc1 += __uint_as_float(q1.z & 0xFFFF0000u) * h[13];
            acc0 += __uint_as_float(q1.w << 16)         * h[14];
            acc1 += __uint_as_float(q1.w & 0xFFFF0000u) * h[15];
            float acc = acc0 + acc1;
            #pragma unroll
            for (int s = 16; s > 0; s >>= 1)
                acc += __shfl_xor_sync(0xffffffffu, acc, s);
            if (l == 0) sacc[kq * RMAX + r] = acc;     // per-quarter, no atomics
        }
        __syncthreads();

        // -- epilogue: gates -> (c, h) for this CTA's units -------------------
        if (tid < U) {
            float gi = xgi, gf = xgf, gg = xgg, go = xgo;
            #pragma unroll
            for (int q = 0; q < 4; q++) {
                gi += sacc[q * RMAX + 0*U + tid];
                gf += sacc[q * RMAX + 1*U + tid];
                gg += sacc[q * RMAX + 2*U + tid];
                go += sacc[q * RMAX + 3*U + tid];
            }
            float ig = sigf(gi);
            float fg = sigf(gf);
            float gt = tanhf(gg);
            float og = sigf(go);
            c_state = fg * c_state + ig * gt;
            g_h[(t + 1) & 1][u0 + tid] = og * tanhf(c_state);
        }
        grid_barrier(b, (unsigned)(t + 2));
    }
}

__global__ void __launch_bounds__(NTHR) lstm_recurrent(const float* __restrict__ W_hh)
{
    const int b = blockIdx.x;
    if (b < 124) lstm_body<14>(b, b * 14, W_hh);
    else         lstm_body<13>(b, 124 * 14 + (b - 124) * 13, W_hh);
}

// ====================== Kernel 3: out = h_T @ W_lin^T + b_lin ===============
__global__ void __launch_bounds__(256) final_linear(
    const float* __restrict__ W_lin, const float* __restrict__ b_lin, float* out)
{
    __shared__ float red[256];
    float s = 0.f;
    // T_STEPS even -> final h lives in buffer 0
    for (int k = threadIdx.x; k < HSZ; k += 256)
        s += g_h[0][k] * W_lin[k];
    red[threadIdx.x] = s;
    __syncthreads();
    for (int o = 128; o > 0; o >>= 1) {
        if (threadIdx.x < o) red[threadIdx.x] += red[threadIdx.x + o];
        __syncthreads();
    }
    if (threadIdx.x == 0) out[0] = red[0] + b_lin[0];

    // reset barrier state so graph replays are deterministic
    for (int i = threadIdx.x; i < NBLK * 32; i += 256) g_rel[i] = 0u;
    if (threadIdx.x < 8) g_cnt[threadIdx.x * 32] = 0u;
}

// ============================================================================
extern "C" void kernel_launch(void* const* d_in, const int* in_sizes, int n_in,
                              void* d_out, int out_size)
{
    const float* input = (const float*)d_in[0];
    const float* W_ih  = (const float*)d_in[1];
    const float* W_hh  = (const float*)d_in[2];
    const float* b_ih  = (const float*)d_in[3];
    const float* b_hh  = (const float*)d_in[4];
    const float* W_lin = (const float*)d_in[5];
    const float* b_lin = (const float*)d_in[6];

    dim3 g1(GSZ / BN, T_STEPS / BM);
    gemm_xgates<<<g1, 256>>>(input, W_ih, b_ih, b_hh);

    const int smem_bytes = RMAX * 1024 * 4 + 4 * RMAX * 4;   // 230,272 B
    cudaFuncSetAttribute(lstm_recurrent,
                         cudaFuncAttributeMaxDynamicSharedMemorySize, smem_bytes);
    lstm_recurrent<<<NBLK, NTHR, smem_bytes>>>(W_hh);

    final_linear<<<1, 256>>>(W_lin, b_lin, (float*)d_out);
}

// round 7
// speedup vs baseline: 1.3744x; 1.2162x over previous
#include <cuda_runtime.h>
#include <cuda_bf16.h>
#include <cstdint>

#define T_STEPS 4096
#define ISZ 512
#define HSZ 2048
#define GSZ (4*HSZ)          // 8192 gate rows
#define NBLK 148             // persistent CTAs (1 per SM, forced by smem)
#define NTHR 512
#define RMAX 56              // padded gate rows per CTA (4*14)

// ---------------- static device scratch (no allocations allowed) ------------
__device__ float g_X[(size_t)T_STEPS * GSZ];   // precomputed input gates
__device__ float g_h[2][HSZ];                  // double-buffered hidden state
__device__ unsigned g_cnt[8 * 32];             // 8 arrival counters, 128B apart

// ---------------- flag ops --------------------------------------------------
__device__ __forceinline__ void red_release_add(unsigned* p, unsigned v) {
    asm volatile("red.release.gpu.global.add.u32 [%0], %1;"
                 :: "l"(p), "r"(v) : "memory");
}
__device__ __forceinline__ unsigned ld_relaxed_gpu(const unsigned* p) {
    unsigned v;
    asm volatile("ld.relaxed.gpu.global.u32 %0, [%1];"
                 : "=r"(v) : "l"(p) : "memory");
    return v;
}
__device__ __forceinline__ void fence_acq() {
    asm volatile("fence.acq_rel.gpu;" ::: "memory");
}

// One-hop grid barrier tail (callers guarantee the arriving thread's prior
// stores are ordered: via __syncthreads or __syncwarp as appropriate).
//  arrive : thread0 red.release.add onto 1 of 8 spread counters
//  wait   : threads 0..7 relaxed-poll the 8 counters directly against
//           stamp*group targets, acquire via fence, bar.sync spreads CTA-wide.
// Counters are monotonic within a launch; final_linear resets them so graph
// replays are deterministic. 148 = 4*19 + 4*18 across the 8 counters.
__device__ __forceinline__ void grid_barrier_tail(int b, unsigned stamp) {
    if (threadIdx.x == 0)
        red_release_add(&g_cnt[(b & 7) * 32], 1u);
    if (threadIdx.x < 8) {
        const unsigned gsz  = (threadIdx.x < 4) ? 19u : 18u;
        const unsigned need = stamp * gsz;
        while (ld_relaxed_gpu(&g_cnt[threadIdx.x * 32]) < need) { }
        fence_acq();
    }
    __syncthreads();
}

// ---------------- packed f32x2 MAC: acc2 += expand(w_bf16x2) * h2 -----------
#define FMA2W(acc, w, hh)                                                   \
    asm("{\n\t"                                                             \
        ".reg .b32 lo, hi;\n\t"                                             \
        ".reg .b64 w2;\n\t"                                                 \
        "shl.b32 lo, %1, 16;\n\t"                                           \
        "and.b32 hi, %1, 0xFFFF0000;\n\t"                                   \
        "mov.b64 w2, {lo, hi};\n\t"                                         \
        "fma.rn.f32x2 %0, w2, %2, %0;\n\t"                                  \
        "}" : "+l"(acc) : "r"(w), "l"(hh))

__device__ __forceinline__ float f32x2_hsum(unsigned long long a) {
    unsigned lo, hi;
    asm("mov.b64 {%0, %1}, %2;" : "=r"(lo), "=r"(hi) : "l"(a));
    return __uint_as_float(lo) + __uint_as_float(hi);
}
__device__ __forceinline__ unsigned long long pack_f32x2(float x, float y) {
    unsigned long long r;
    asm("mov.b64 %0, {%1, %2};" : "=l"(r) : "f"(x), "f"(y));
    return r;
}

// ====================== Kernel 1: X = input @ W_ih^T + (b_ih+b_hh) ==========
#define BM 128
#define BN 128
#define BK 16

__global__ void __launch_bounds__(256) gemm_xgates(
    const float* __restrict__ A, const float* __restrict__ B,
    const float* __restrict__ b_ih, const float* __restrict__ b_hh)
{
    __shared__ float As[BK][BM];
    __shared__ float Bs[BK][BN];
    const int tid = threadIdx.x;
    const int tx = tid & 15, ty = tid >> 4;
    const int m0 = blockIdx.y * BM, n0 = blockIdx.x * BN;
    float acc[8][8] = {};

    for (int k0 = 0; k0 < ISZ; k0 += BK) {
        #pragma unroll
        for (int rep = 0; rep < 2; rep++) {
            int row = (tid >> 2) + rep * 64;
            int kg  = (tid & 3) * 4;
            float4 va = *(const float4*)&A[(size_t)(m0 + row) * ISZ + k0 + kg];
            As[kg+0][row] = va.x; As[kg+1][row] = va.y;
            As[kg+2][row] = va.z; As[kg+3][row] = va.w;
            float4 vb = *(const float4*)&B[(size_t)(n0 + row) * ISZ + k0 + kg];
            Bs[kg+0][row] = vb.x; Bs[kg+1][row] = vb.y;
            Bs[kg+2][row] = vb.z; Bs[kg+3][row] = vb.w;
        }
        __syncthreads();
        #pragma unroll
        for (int kk = 0; kk < BK; kk++) {
            float a[8], bb[8];
            float4 a0 = *(const float4*)&As[kk][ty * 8];
            float4 a1 = *(const float4*)&As[kk][ty * 8 + 4];
            float4 b0 = *(const float4*)&Bs[kk][tx * 8];
            float4 b1 = *(const float4*)&Bs[kk][tx * 8 + 4];
            a[0]=a0.x; a[1]=a0.y; a[2]=a0.z; a[3]=a0.w;
            a[4]=a1.x; a[5]=a1.y; a[6]=a1.z; a[7]=a1.w;
            bb[0]=b0.x; bb[1]=b0.y; bb[2]=b0.z; bb[3]=b0.w;
            bb[4]=b1.x; bb[5]=b1.y; bb[6]=b1.z; bb[7]=b1.w;
            #pragma unroll
            for (int i = 0; i < 8; i++)
                #pragma unroll
                for (int j = 0; j < 8; j++)
                    acc[i][j] += a[i] * bb[j];
        }
        __syncthreads();
    }
    #pragma unroll
    for (int i = 0; i < 8; i++) {
        int m = m0 + ty * 8 + i;
        #pragma unroll
        for (int j = 0; j < 8; j++) {
            int n = n0 + tx * 8 + j;
            g_X[(size_t)m * GSZ + n] = acc[i][j] + b_ih[n] + b_hh[n];
        }
    }
}

// ====================== Kernel 2: persistent recurrence =====================
__device__ __forceinline__ float sigf(float x) { return 1.f / (1.f + __expf(-x)); }

template<int U>
__device__ __forceinline__ void lstm_body(const int b, const int u0,
                                          const float* __restrict__ W_hh)
{
    constexpr int R = 4 * U;          // live gate rows (52 or 56)
    extern __shared__ unsigned smem[];
    unsigned* sw = smem;                              // [RMAX][1024] bf16x2
    float* sacc  = (float*)(smem + RMAX * 1024);      // [4][RMAX] partials

    const int tid = threadIdx.x;

    // ---- stage W_hh slice as packed bf16 pairs; pad rows >= R with zeros ----
    for (int idx = tid; idx < RMAX * 1024; idx += NTHR) {
        const int r  = idx >> 10;
        const int k2 = idx & 1023;
        unsigned packed = 0u;
        if (r < R) {
            const int grow = (r / U) * HSZ + u0 + (r % U);
            float2 w2 = *(const float2*)&W_hh[(size_t)grow * HSZ + 2 * k2];
            unsigned lo = (unsigned)__bfloat16_as_ushort(__float2bfloat16(w2.x));
            unsigned hi = (unsigned)__bfloat16_as_ushort(__float2bfloat16(w2.y));
            packed = (hi << 16) | lo;
        }
        sw[idx] = packed;
    }
    float c_state = 0.f;
    if (tid < U) g_h[0][u0 + tid] = 0.f;
    __syncthreads();                  // staging + h zeros done CTA-wide
    grid_barrier_tail(b, 1u);

    const int w = tid >> 5, l = tid & 31;
    const int kq = w >> 2;            // K quarter (0..3), 512 columns each
    const int wr = w & 3;             // row slot (0..3)
    const uint4* wbase = (const uint4*)sw;
    const bool hi_half = (l >= 16);

    for (int t = 0; t < T_STEPS; t++) {
        // -- prefetch this step's x-gate terms (latency hides under MAC) -----
        float xgi = 0.f, xgf = 0.f, xgg = 0.f, xgo = 0.f;
        if (tid < U) {
            const float* xg = &g_X[(size_t)t * GSZ + u0 + tid];
            xgi = __ldcs(xg);
            xgf = __ldcs(xg + HSZ);
            xgg = __ldcs(xg + 2 * HSZ);
            xgo = __ldcs(xg + 3 * HSZ);
        }

        // -- load this warp's 512-wide h quarter, packed as f32x2 pairs ------
        unsigned long long h2[8];
        {
            const float4* hb = (const float4*)&g_h[t & 1][kq * 512];
            float4 a0 = __ldcg(hb + l * 2);
            float4 a1 = __ldcg(hb + l * 2 + 1);
            float4 a2 = __ldcg(hb + 64 + l * 2);
            float4 a3 = __ldcg(hb + 64 + l * 2 + 1);
            h2[0] = pack_f32x2(a0.x, a0.y);
            h2[1] = pack_f32x2(a0.z, a0.w);
            h2[2] = pack_f32x2(a1.x, a1.y);
            h2[3] = pack_f32x2(a1.z, a1.w);
            h2[4] = pack_f32x2(a2.x, a2.y);
            h2[5] = pack_f32x2(a2.z, a2.w);
            h2[6] = pack_f32x2(a3.x, a3.y);
            h2[7] = pack_f32x2(a3.z, a3.w);
        }

        // -- MAC: 14 rows per warp as 7 row-pairs, FFMA2 + paired reduce -----
        #pragma unroll
        for (int rp = 0; rp < 7; rp++) {
            const int rA = wr + (2 * rp)     * 4;
            const int rB = wr + (2 * rp + 1) * 4;
            const uint4* wpA = wbase + rA * 256 + kq * 64 + l;
            const uint4* wpB = wbase + rB * 256 + kq * 64 + l;
            unsigned long long accA = 0ull, accB = 0ull;   // f32x2 {0,0}
            uint4 qa0 = wpA[0];
            FMA2W(accA, qa0.x, h2[0]); FMA2W(accA, qa0.y, h2[1]);
            FMA2W(accA, qa0.z, h2[2]); FMA2W(accA, qa0.w, h2[3]);
            uint4 qa1 = wpA[32];
            FMA2W(accA, qa1.x, h2[4]); FMA2W(accA, qa1.y, h2[5]);
            FMA2W(accA, qa1.z, h2[6]); FMA2W(accA, qa1.w, h2[7]);
            uint4 qb0 = wpB[0];
            FMA2W(accB, qb0.x, h2[0]); FMA2W(accB, qb0.y, h2[1]);
            FMA2W(accB, qb0.z, h2[2]); FMA2W(accB, qb0.w, h2[3]);
            uint4 qb1 = wpB[32];
            FMA2W(accB, qb1.x, h2[4]); FMA2W(accB, qb1.y, h2[5]);
            FMA2W(accB, qb1.z, h2[6]); FMA2W(accB, qb1.w, h2[7]);

            float zA = f32x2_hsum(accA);
            float zB = f32x2_hsum(accB);
            // paired reduce: rows A (lanes 0-15) and B (lanes 16-31) share
            // one 5-level tree; level 1 exchanges the opposite row's value.
            float z = hi_half ? zB : zA;
            float u = hi_half ? zA : zB;
            z += __shfl_xor_sync(0xffffffffu, u, 16);
            z += __shfl_xor_sync(0xffffffffu, z, 8);
            z += __shfl_xor_sync(0xffffffffu, z, 4);
            z += __shfl_xor_sync(0xffffffffu, z, 2);
            z += __shfl_xor_sync(0xffffffffu, z, 1);
            if (l == 0)  sacc[kq * RMAX + rA] = z;
            if (l == 16) sacc[kq * RMAX + rB] = z;
        }
        __syncthreads();              // sacc ready CTA-wide

        // -- epilogue in warp 0 only: gates -> (c, h) -------------------------
        if (tid < U) {
            float gi = xgi, gf = xgf, gg = xgg, go = xgo;
            #pragma unroll
            for (int q = 0; q < 4; q++) {
                gi += sacc[q * RMAX + 0*U + tid];
                gf += sacc[q * RMAX + 1*U + tid];
                gg += sacc[q * RMAX + 2*U + tid];
                go += sacc[q * RMAX + 3*U + tid];
            }
            float ig = sigf(gi);
            float fg = sigf(gf);
            float gt = tanhf(gg);
            float og = sigf(go);
            c_state = fg * c_state + ig * gt;
            g_h[(t + 1) & 1][u0 + tid] = og * tanhf(c_state);
        }
        if (w == 0) __syncwarp();     // warp0's h stores done before arrival
        grid_barrier_tail(b, (unsigned)(t + 2));
    }
}

__global__ void __launch_bounds__(NTHR) lstm_recurrent(const float* __restrict__ W_hh)
{
    const int b = blockIdx.x;
    if (b < 124) lstm_body<14>(b, b * 14, W_hh);
    else         lstm_body<13>(b, 124 * 14 + (b - 124) * 13, W_hh);
}

// ====================== Kernel 3: out = h_T @ W_lin^T + b_lin ===============
__global__ void __launch_bounds__(256) final_linear(
    const float* __restrict__ W_lin, const float* __restrict__ b_lin, float* out)
{
    __shared__ float red[256];
    float s = 0.f;
    // T_STEPS even -> final h lives in buffer 0
    for (int k = threadIdx.x; k < HSZ; k += 256)
        s += g_h[0][k] * W_lin[k];
    red[threadIdx.x] = s;
    __syncthreads();
    for (int o = 128; o > 0; o >>= 1) {
        if (threadIdx.x < o) red[threadIdx.x] += red[threadIdx.x + o];
        __syncthreads();
    }
    if (threadIdx.x == 0) out[0] = red[0] + b_lin[0];

    // reset barrier counters so graph replays are deterministic
    if (threadIdx.x < 8) g_cnt[threadIdx.x * 32] = 0u;
}

// ============================================================================
extern "C" void kernel_launch(void* const* d_in, const int* in_sizes, int n_in,
                              void* d_out, int out_size)
{
    const float* input = (const float*)d_in[0];
    const float* W_ih  = (const float*)d_in[1];
    const float* W_hh  = (const float*)d_in[2];
    const float* b_ih  = (const float*)d_in[3];
    const float* b_hh  = (const float*)d_in[4];
    const float* W_lin = (const float*)d_in[5];
    const float* b_lin = (const float*)d_in[6];

    dim3 g1(GSZ / BN, T_STEPS / BM);
    gemm_xgates<<<g1, 256>>>(input, W_ih, b_ih, b_hh);

    const int smem_bytes = RMAX * 1024 * 4 + 4 * RMAX * 4;   // 230,272 B
    cudaFuncSetAttribute(lstm_recurrent,
                         cudaFuncAttributeMaxDynamicSharedMemorySize, smem_bytes);
    lstm_recurrent<<<NBLK, NTHR, smem_bytes>>>(W_hh);

    final_linear<<<1, 256>>>(W_lin, b_lin, (float*)d_out);
}